// round 2
// baseline (speedup 1.0000x reference)
#include <cuda_runtime.h>

#define BATCH 4
#define CCH   256
#define C8    32
#define HWSZ  4096

// Scratch (device globals — allocation-free per harness rules)
__device__ float g_Q[(size_t)BATCH * HWSZ * C8];
__device__ float g_K[(size_t)BATCH * HWSZ * C8];
__device__ float g_V[(size_t)BATCH * CCH * HWSZ];
__device__ float g_S[(size_t)BATCH * HWSZ * HWSZ];   // 268 MB: S, then P in place

// ---------------------------------------------------------------------------
// Kernel 1: Q/K projections.  Q[b,i,o] = sum_c wq[o,c]*x[b,c,i] + bq[o]
// grid (HW/64, B), 256 threads. Each block: 64 pixels, all 64 outputs (32 q + 32 k).
// ---------------------------------------------------------------------------
__global__ void __launch_bounds__(256) proj_qk_kernel(
        const float* __restrict__ x,
        const float* __restrict__ wq, const float* __restrict__ bq,
        const float* __restrict__ wk, const float* __restrict__ bk) {
    __shared__ float xs[64][64];   // [c_chunk][px]
    __shared__ float ws[64][64];   // [out][c_chunk]
    int t  = threadIdx.x;
    int b  = blockIdx.y;
    int i0 = blockIdx.x * 64;
    int px = t & 63;
    int r  = t >> 6;               // 0..3 -> outputs r*16 .. r*16+15
    float acc[16];
#pragma unroll
    for (int u = 0; u < 16; ++u) acc[u] = 0.f;
    const float* xb = x + (size_t)b * CCH * HWSZ;
    for (int c0 = 0; c0 < CCH; c0 += 64) {
#pragma unroll
        for (int rr = 0; rr < 16; ++rr) {
            int cc = r + rr * 4;
            xs[cc][px] = xb[(size_t)(c0 + cc) * HWSZ + i0 + px];
        }
        {
            int cc = t & 63;
#pragma unroll
            for (int rr = 0; rr < 16; ++rr) {
                int o = r + rr * 4;
                ws[o][cc] = (o < 32) ? wq[o * CCH + c0 + cc]
                                     : wk[(o - 32) * CCH + c0 + cc];
            }
        }
        __syncthreads();
#pragma unroll 4
        for (int cc = 0; cc < 64; ++cc) {
            float xv = xs[cc][px];
#pragma unroll
            for (int u = 0; u < 16; ++u)
                acc[u] += ws[r * 16 + u][cc] * xv;
        }
        __syncthreads();
    }
    int i = i0 + px;
#pragma unroll
    for (int u = 0; u < 16; ++u) {
        int o = r * 16 + u;
        if (o < 32)
            g_Q[((size_t)b * HWSZ + i) * C8 + o] = acc[u] + bq[o];
        else
            g_K[((size_t)b * HWSZ + i) * C8 + (o - 32)] = acc[u] + bk[o - 32];
    }
}

// ---------------------------------------------------------------------------
// Kernel 2: V projection. V[b,c,i] = sum_c' wv[c,c']*orig[b,c',i] + bv[c]
// grid (HW/128, C/64, B), 256 threads. Tile 64c x 128px, K-chunks of 32.
// ---------------------------------------------------------------------------
__global__ void __launch_bounds__(256) proj_v_kernel(
        const float* __restrict__ orig,
        const float* __restrict__ wv, const float* __restrict__ bv) {
    __shared__ float wst[32][68];   // [k][c]  (transposed)
    __shared__ float os[32][128];   // [k][px]
    int t = threadIdx.x;
    int b = blockIdx.z;
    int cblk = blockIdx.y * 64;
    int i1 = blockIdx.x * 128;
    int tx = t & 15, ty = t >> 4;
    float acc[4][8];
#pragma unroll
    for (int a = 0; a < 4; ++a)
#pragma unroll
        for (int p = 0; p < 8; ++p) acc[a][p] = 0.f;
    const float* ob = orig + (size_t)b * CCH * HWSZ;
    for (int k0 = 0; k0 < CCH; k0 += 32) {
#pragma unroll
        for (int rr = 0; rr < 2; ++rr) {
            int f = t + rr * 256;
            int cc = f >> 3;
            int k4 = f & 7;
            float4 w4 = *(const float4*)(wv + (size_t)(cblk + cc) * CCH + k0 + k4 * 4);
            wst[k4 * 4 + 0][cc] = w4.x;
            wst[k4 * 4 + 1][cc] = w4.y;
            wst[k4 * 4 + 2][cc] = w4.z;
            wst[k4 * 4 + 3][cc] = w4.w;
        }
#pragma unroll
        for (int rr = 0; rr < 4; ++rr) {
            int f = t + rr * 256;
            int kk = f >> 5;
            int p4 = f & 31;
            *(float4*)&os[kk][p4 * 4] =
                *(const float4*)(ob + (size_t)(k0 + kk) * HWSZ + i1 + p4 * 4);
        }
        __syncthreads();
#pragma unroll 4
        for (int k = 0; k < 32; ++k) {
            float4 w4  = *(const float4*)&wst[k][ty * 4];
            float4 oa  = *(const float4*)&os[k][tx * 4];
            float4 ob4 = *(const float4*)&os[k][64 + tx * 4];
            float wf[4] = {w4.x, w4.y, w4.z, w4.w};
            float of[8] = {oa.x, oa.y, oa.z, oa.w, ob4.x, ob4.y, ob4.z, ob4.w};
#pragma unroll
            for (int a = 0; a < 4; ++a)
#pragma unroll
                for (int p = 0; p < 8; ++p)
                    acc[a][p] += wf[a] * of[p];
        }
        __syncthreads();
    }
#pragma unroll
    for (int a = 0; a < 4; ++a) {
        int c = cblk + ty * 4 + a;
        float bias = bv[c];
        float* vrow = g_V + ((size_t)b * CCH + c) * HWSZ + i1;
        *(float4*)(vrow + tx * 4) =
            make_float4(acc[a][0] + bias, acc[a][1] + bias, acc[a][2] + bias, acc[a][3] + bias);
        *(float4*)(vrow + 64 + tx * 4) =
            make_float4(acc[a][4] + bias, acc[a][5] + bias, acc[a][6] + bias, acc[a][7] + bias);
    }
}

// ---------------------------------------------------------------------------
// Kernel 3: S[b,i,j] = sum_k Q[b,i,k]*K[b,j,k].  grid (HW/64, HW/64, B).
// Tile 64x64, K=32 single shot, 4x4 per thread.
// ---------------------------------------------------------------------------
__global__ void __launch_bounds__(256) qk_gemm_kernel() {
    __shared__ float qs[64][36];
    __shared__ float ks[64][36];
    int t = threadIdx.x;
    int b = blockIdx.z;
    int i0 = blockIdx.y * 64;
    int j0 = blockIdx.x * 64;
    int tj = t & 15, ti = t >> 4;
#pragma unroll
    for (int rr = 0; rr < 2; ++rr) {
        int f = t + rr * 256;
        int row = f >> 3;
        int k4 = f & 7;
        *(float4*)&qs[row][k4 * 4] =
            *(const float4*)(g_Q + ((size_t)b * HWSZ + i0 + row) * C8 + k4 * 4);
        *(float4*)&ks[row][k4 * 4] =
            *(const float4*)(g_K + ((size_t)b * HWSZ + j0 + row) * C8 + k4 * 4);
    }
    __syncthreads();
    float acc[4][4] = {};
#pragma unroll
    for (int k = 0; k < 32; ++k) {
        float qv[4], kv[4];
#pragma unroll
        for (int u = 0; u < 4; ++u) {
            qv[u] = qs[ti * 4 + u][k];
            kv[u] = ks[tj * 4 + u][k];
        }
#pragma unroll
        for (int ii = 0; ii < 4; ++ii)
#pragma unroll
            for (int jj = 0; jj < 4; ++jj)
                acc[ii][jj] += qv[ii] * kv[jj];
    }
#pragma unroll
    for (int ii = 0; ii < 4; ++ii) {
        size_t off = ((size_t)b * HWSZ + i0 + ti * 4 + ii) * HWSZ + j0 + tj * 4;
        *(float4*)(g_S + off) = make_float4(acc[ii][0], acc[ii][1], acc[ii][2], acc[ii][3]);
    }
}

// ---------------------------------------------------------------------------
// Kernel 4: row softmax in place on g_S.  grid (HW, B), 256 threads / row.
// Each thread holds its 16 elements in registers (no row smem).
// ---------------------------------------------------------------------------
__global__ void __launch_bounds__(256) softmax_kernel() {
    __shared__ float red[8];
    int t = threadIdx.x;
    int b = blockIdx.y;
    int i = blockIdx.x;
    float* row = g_S + ((size_t)b * HWSZ + i) * HWSZ;
    float4 v[4];
#pragma unroll
    for (int r = 0; r < 4; ++r)
        v[r] = *(const float4*)(row + (t + r * 256) * 4);
    float m = -1e30f;
#pragma unroll
    for (int r = 0; r < 4; ++r)
        m = fmaxf(m, fmaxf(fmaxf(v[r].x, v[r].y), fmaxf(v[r].z, v[r].w)));
#pragma unroll
    for (int o = 16; o > 0; o >>= 1) m = fmaxf(m, __shfl_xor_sync(0xffffffffu, m, o));
    if ((t & 31) == 0) red[t >> 5] = m;
    __syncthreads();
    m = red[0];
#pragma unroll
    for (int w = 1; w < 8; ++w) m = fmaxf(m, red[w]);
    float s = 0.f;
#pragma unroll
    for (int r = 0; r < 4; ++r) {
        v[r].x = __expf(v[r].x - m); v[r].y = __expf(v[r].y - m);
        v[r].z = __expf(v[r].z - m); v[r].w = __expf(v[r].w - m);
        s += v[r].x + v[r].y + v[r].z + v[r].w;
    }
#pragma unroll
    for (int o = 16; o > 0; o >>= 1) s += __shfl_xor_sync(0xffffffffu, s, o);
    __syncthreads();                    // red reuse
    if ((t & 31) == 0) red[t >> 5] = s;
    __syncthreads();
    s = 0.f;
#pragma unroll
    for (int w = 0; w < 8; ++w) s += red[w];
    float inv = 1.f / s;
#pragma unroll
    for (int r = 0; r < 4; ++r) {
        v[r].x *= inv; v[r].y *= inv; v[r].z *= inv; v[r].w *= inv;
        *(float4*)(row + (t + r * 256) * 4) = v[r];
    }
}

// ---------------------------------------------------------------------------
// Kernel 5: out[b,c,i] = gamma * sum_j V[b,c,j]*P[b,i,j] + input[b,c,i]
// grid (HW/64, C/128, B), 256 threads.  Tile 128c x 64i, K-chunks of 32.
// Per thread: 8c x 4i accumulators.
// ---------------------------------------------------------------------------
__global__ void __launch_bounds__(256) av_kernel(
        const float* __restrict__ inp,
        const float* __restrict__ gamma,
        float* __restrict__ outp) {
    __shared__ float vs[128][36];   // [c][j]
    __shared__ float ps[64][36];    // [i][j]
    int t  = threadIdx.x;
    int b  = blockIdx.z;
    int ct = blockIdx.y * 128;
    int it = blockIdx.x * 64;
    int tx = t & 15, ty = t >> 4;
    const float* Vb = g_V + ((size_t)b * CCH + ct) * HWSZ;
    const float* Pb = g_S + ((size_t)b * HWSZ + it) * HWSZ;
    float acc[8][4] = {};
    int jj4   = t & 7;
    int rbase = t >> 3;             // 0..31
    for (int j0 = 0; j0 < HWSZ; j0 += 32) {
#pragma unroll
        for (int rr = 0; rr < 4; ++rr) {
            int c = rbase + rr * 32;
            *(float4*)&vs[c][jj4 * 4] =
                *(const float4*)(Vb + (size_t)c * HWSZ + j0 + jj4 * 4);
        }
#pragma unroll
        for (int rr = 0; rr < 2; ++rr) {
            int i = rbase + rr * 32;
            *(float4*)&ps[i][jj4 * 4] =
                *(const float4*)(Pb + (size_t)i * HWSZ + j0 + jj4 * 4);
        }
        __syncthreads();
#pragma unroll 8
        for (int jj = 0; jj < 32; ++jj) {
            float a[8], pv[4];
#pragma unroll
            for (int u = 0; u < 4; ++u) {
                a[u]     = vs[ty * 4 + u][jj];
                a[4 + u] = vs[64 + ty * 4 + u][jj];
                pv[u]    = ps[tx * 4 + u][jj];
            }
#pragma unroll
            for (int cu = 0; cu < 8; ++cu)
#pragma unroll
                for (int iu = 0; iu < 4; ++iu)
                    acc[cu][iu] += a[cu] * pv[iu];
        }
        __syncthreads();
    }
    float g = *gamma;
    int iglob = it + tx * 4;
#pragma unroll
    for (int cu = 0; cu < 8; ++cu) {
        int c = ct + ((cu < 4) ? (ty * 4 + cu) : (64 + ty * 4 + (cu - 4)));
        size_t off = ((size_t)b * CCH + c) * HWSZ + iglob;
        float4 iv = *(const float4*)(inp + off);
        *(float4*)(outp + off) = make_float4(
            g * acc[cu][0] + iv.x, g * acc[cu][1] + iv.y,
            g * acc[cu][2] + iv.z, g * acc[cu][3] + iv.w);
    }
}

// ---------------------------------------------------------------------------
extern "C" void kernel_launch(void* const* d_in, const int* in_sizes, int n_in,
                              void* d_out, int out_size) {
    const float* inp   = (const float*)d_in[0];
    const float* orig  = (const float*)d_in[1];
    const float* wq    = (const float*)d_in[2];
    const float* bq    = (const float*)d_in[3];
    const float* wk    = (const float*)d_in[4];
    const float* bk    = (const float*)d_in[5];
    const float* wv    = (const float*)d_in[6];
    const float* bv    = (const float*)d_in[7];
    const float* gamma = (const float*)d_in[8];
    float* outp = (float*)d_out;

    proj_qk_kernel<<<dim3(HWSZ / 64, BATCH), 256>>>(inp, wq, bq, wk, bk);
    proj_v_kernel<<<dim3(HWSZ / 128, CCH / 64, BATCH), 256>>>(orig, wv, bv);
    qk_gemm_kernel<<<dim3(HWSZ / 64, HWSZ / 64, BATCH), 256>>>();
    softmax_kernel<<<dim3(HWSZ, BATCH), 256>>>();
    av_kernel<<<dim3(HWSZ / 64, CCH / 128, BATCH), 256>>>(inp, gamma, outp);
}

// round 17
// speedup vs baseline: 4.3896x; 4.3896x over previous
#include <cuda_runtime.h>
#include <cuda_fp16.h>

typedef unsigned int u32;
typedef unsigned long long u64;
typedef unsigned short u16;

constexpr int BATCH = 4;
constexpr int CCH   = 256;
constexpr int HWSZ  = 4096;

// ---------------- device scratch (allocation-free) ----------------
__device__ float  g_S  [(size_t)BATCH * HWSZ * HWSZ];
__device__ __half g_P  [(size_t)BATCH * HWSZ * HWSZ];
__device__ __half g_Vhi[(size_t)BATCH * CCH * HWSZ];
__device__ __half g_Vlo[(size_t)BATCH * CCH * HWSZ];
__device__ __half g_Qpk[(size_t)BATCH * HWSZ * 64];   // [hi(32) | lo(32)] per row
__device__ __half g_Kpk[(size_t)BATCH * HWSZ * 64];

// ---------------- PTX wrappers (baseline ISA only: sm_80-level) ----------
__device__ __forceinline__ u32 smem_u32(const void* p) {
    u32 a;
    asm("{ .reg .u64 t1; cvta.to.shared.u64 t1, %1; cvt.u32.u64 %0, t1; }" : "=r"(a) : "l"(p));
    return a;
}
__device__ __forceinline__ void cpa16(u32 dst, const void* src) {
    asm volatile("cp.async.cg.shared.global [%0], [%1], 16;" :: "r"(dst), "l"(src));
}
__device__ __forceinline__ void cp_commit() {
    asm volatile("cp.async.commit_group;" ::: "memory");
}
__device__ __forceinline__ void cp_wait0() {
    asm volatile("cp.async.wait_group 0;" ::: "memory");
}
__device__ __forceinline__ void cp_wait1() {
    asm volatile("cp.async.wait_group 1;" ::: "memory");
}
__device__ __forceinline__ void ldm_x4(u32* r, u32 addr) {
    asm volatile("ldmatrix.sync.aligned.m8n8.x4.shared.b16 {%0, %1, %2, %3}, [%4];" : "=r"(r[0]), "=r"(r[1]), "=r"(r[2]), "=r"(r[3]) : "r"(addr));
}
__device__ __forceinline__ void mma16816(float* d, const u32* a, u32 b0, u32 b1) {
    asm volatile("mma.sync.aligned.m16n8k16.row.col.f32.f16.f16.f32 {%0, %1, %2, %3}, {%4, %5, %6, %7}, {%8, %9}, {%0, %1, %2, %3};" : "+f"(d[0]), "+f"(d[1]), "+f"(d[2]), "+f"(d[3]) : "r"(a[0]), "r"(a[1]), "r"(a[2]), "r"(a[3]), "r"(b0), "r"(b1));
}

__device__ __forceinline__ void store4_hilo(__half* ph, __half* pl,
                                            float a, float b, float c, float d) {
    float v[4];
    v[0] = a; v[1] = b; v[2] = c; v[3] = d;
    u64 uh = 0ull, ul = 0ull;
#pragma unroll
    for (int i = 0; i < 4; ++i) {
        __half h = __float2half(v[i]);
        __half l = __float2half(v[i] - __half2float(h));
        uh |= (u64)__half_as_ushort(h) << (16 * i);
        ul |= (u64)__half_as_ushort(l) << (16 * i);
    }
    *(u64*)ph = uh;
    *(u64*)pl = ul;
}

// ---------------------------------------------------------------------------
// Kernel 1: Q/K projections -> packed fp16 hi/lo rows [b, i, 64]
// ---------------------------------------------------------------------------
__global__ void __launch_bounds__(256) proj_qk_kernel(
        const float* __restrict__ x,
        const float* __restrict__ wq, const float* __restrict__ bq,
        const float* __restrict__ wk, const float* __restrict__ bk) {
    __shared__ float xs[64][64];
    __shared__ float ws[64][64];
    int t  = threadIdx.x;
    int b  = blockIdx.y;
    int i0 = blockIdx.x * 64;
    int px = t & 63;
    int r  = t >> 6;
    float acc[16];
#pragma unroll
    for (int u = 0; u < 16; ++u) acc[u] = 0.f;
    const float* xb = x + (size_t)b * CCH * HWSZ;
    for (int c0 = 0; c0 < CCH; c0 += 64) {
#pragma unroll
        for (int rr = 0; rr < 16; ++rr) {
            int cc = r + rr * 4;
            xs[cc][px] = xb[(size_t)(c0 + cc) * HWSZ + i0 + px];
        }
        {
            int cc = t & 63;
#pragma unroll
            for (int rr = 0; rr < 16; ++rr) {
                int o = r + rr * 4;
                ws[o][cc] = (o < 32) ? wq[o * CCH + c0 + cc]
                                     : wk[(o - 32) * CCH + c0 + cc];
            }
        }
        __syncthreads();
#pragma unroll 4
        for (int cc = 0; cc < 64; ++cc) {
            float xv = xs[cc][px];
#pragma unroll
            for (int u = 0; u < 16; ++u)
                acc[u] += ws[r * 16 + u][cc] * xv;
        }
        __syncthreads();
    }
    int i = i0 + px;
#pragma unroll
    for (int u = 0; u < 16; ++u) {
        int o = r * 16 + u;
        float val;
        __half* base;
        int oo;
        if (o < 32) {
            val = acc[u] + bq[o];
            base = g_Qpk + ((size_t)b * HWSZ + i) * 64;
            oo = o;
        } else {
            val = acc[u] + bk[o - 32];
            base = g_Kpk + ((size_t)b * HWSZ + i) * 64;
            oo = o - 32;
        }
        __half h = __float2half(val);
        base[oo]      = h;
        base[32 + oo] = __float2half(val - __half2float(h));
    }
}

// ---------------------------------------------------------------------------
// Kernel 2: V projection -> g_Vhi/g_Vlo fp16 [b, c, i]
// ---------------------------------------------------------------------------
__global__ void __launch_bounds__(256) proj_v_kernel(
        const float* __restrict__ orig,
        const float* __restrict__ wv, const float* __restrict__ bv) {
    __shared__ float wst[32][68];
    __shared__ float os[32][128];
    int t = threadIdx.x;
    int b = blockIdx.z;
    int cblk = blockIdx.y * 64;
    int i1 = blockIdx.x * 128;
    int tx = t & 15;
    int ty = t >> 4;
    float acc[4][8];
#pragma unroll
    for (int a = 0; a < 4; ++a) {
#pragma unroll
        for (int p = 0; p < 8; ++p) acc[a][p] = 0.f;
    }
    const float* ob = orig + (size_t)b * CCH * HWSZ;
    for (int k0 = 0; k0 < CCH; k0 += 32) {
#pragma unroll
        for (int rr = 0; rr < 2; ++rr) {
            int f = t + rr * 256;
            int cc = f >> 3;
            int k4 = f & 7;
            float4 w4 = *(const float4*)(wv + (size_t)(cblk + cc) * CCH + k0 + k4 * 4);
            wst[k4 * 4 + 0][cc] = w4.x;
            wst[k4 * 4 + 1][cc] = w4.y;
            wst[k4 * 4 + 2][cc] = w4.z;
            wst[k4 * 4 + 3][cc] = w4.w;
        }
#pragma unroll
        for (int rr = 0; rr < 4; ++rr) {
            int f = t + rr * 256;
            int kk = f >> 5;
            int p4 = f & 31;
            *(float4*)&os[kk][p4 * 4] =
                *(const float4*)(ob + (size_t)(k0 + kk) * HWSZ + i1 + p4 * 4);
        }
        __syncthreads();
#pragma unroll 4
        for (int k = 0; k < 32; ++k) {
            float4 w4  = *(const float4*)&wst[k][ty * 4];
            float4 oa  = *(const float4*)&os[k][tx * 4];
            float4 ob4 = *(const float4*)&os[k][64 + tx * 4];
            float wf[4];
            float of[8];
            wf[0] = w4.x; wf[1] = w4.y; wf[2] = w4.z; wf[3] = w4.w;
            of[0] = oa.x; of[1] = oa.y; of[2] = oa.z; of[3] = oa.w;
            of[4] = ob4.x; of[5] = ob4.y; of[6] = ob4.z; of[7] = ob4.w;
#pragma unroll
            for (int a = 0; a < 4; ++a) {
#pragma unroll
                for (int p = 0; p < 8; ++p)
                    acc[a][p] += wf[a] * of[p];
            }
        }
        __syncthreads();
    }
#pragma unroll
    for (int a = 0; a < 4; ++a) {
        int c = cblk + ty * 4 + a;
        float bias = bv[c];
        size_t roff = ((size_t)b * CCH + c) * HWSZ + i1;
        store4_hilo(g_Vhi + roff + tx * 4, g_Vlo + roff + tx * 4,
                    acc[a][0] + bias, acc[a][1] + bias, acc[a][2] + bias, acc[a][3] + bias);
        store4_hilo(g_Vhi + roff + 64 + tx * 4, g_Vlo + roff + 64 + tx * 4,
                    acc[a][4] + bias, acc[a][5] + bias, acc[a][6] + bias, acc[a][7] + bias);
    }
}

// ---------------------------------------------------------------------------
// Kernel 3: QK^T via mma.sync, fp16 hi/lo split (3 products, 6 k16 steps).
// Tile 128x128, 8 warps as 2(M)x4(N), warp tile 64x32. S fp32 out.
// ---------------------------------------------------------------------------
__global__ void __launch_bounds__(256) qk_mma_kernel() {
    __shared__ __align__(1024) char tiles[32768];   // Q 16KB | K 16KB
    int t = threadIdx.x;
    int lane = t & 31;
    int wid = t >> 5;
    int b = blockIdx.z;
    int i0 = blockIdx.y * 128;
    int j0 = blockIdx.x * 128;
    int wm = wid & 1;
    int wn = wid >> 1;
    u32 qs = smem_u32(tiles);
    u32 ks = qs + 16384u;

    int row = t & 127;
    int cb = (t >> 7) * 4;
    const __half* qg = g_Qpk + ((size_t)b * HWSZ + i0 + row) * 64;
    const __half* kg = g_Kpk + ((size_t)b * HWSZ + j0 + row) * 64;
    u32 ro = (u32)row * 128u;
#pragma unroll
    for (int i = 0; i < 4; ++i) {
        int ch = cb + i;
        u32 sw = (u32)((ch ^ (row & 7)) << 4);
        cpa16(qs + ro + sw, qg + ch * 8);
        cpa16(ks + ro + sw, kg + ch * 8);
    }
    cp_commit();
    cp_wait0();
    __syncthreads();

    float acc[4][4][4];
#pragma unroll
    for (int a = 0; a < 4; ++a) {
#pragma unroll
        for (int n = 0; n < 4; ++n) {
#pragma unroll
            for (int e = 0; e < 4; ++e) acc[a][n][e] = 0.f;
        }
    }

    // chunk bases (16B units): hi = chunks 0-3, lo = chunks 4-7.
    // products: hi*hi, hi*lo, lo*hi
    const int ap[6] = {0, 2, 0, 2, 4, 6};
    const int bp[6] = {0, 2, 4, 6, 0, 2};
#pragma unroll
    for (int s = 0; s < 6; ++s) {
        u32 afr[4][4];
        u32 bfr[2][4];
#pragma unroll
        for (int mf = 0; mf < 4; ++mf) {
            int rowA = wm * 64 + mf * 16 + (lane & 15);
            int ch = ap[s] + (lane >> 4);
            ldm_x4(afr[mf], qs + (u32)rowA * 128u + (u32)((ch ^ (rowA & 7)) << 4));
        }
#pragma unroll
        for (int g = 0; g < 2; ++g) {
            int rowB = wn * 32 + g * 16 + (lane & 7) + ((lane >> 4) << 3);
            int ch = bp[s] + ((lane >> 3) & 1);
            ldm_x4(bfr[g], ks + (u32)rowB * 128u + (u32)((ch ^ (rowB & 7)) << 4));
        }
#pragma unroll
        for (int mf = 0; mf < 4; ++mf) {
#pragma unroll
            for (int g = 0; g < 2; ++g) {
                mma16816(acc[mf][2 * g],     afr[mf], bfr[g][0], bfr[g][1]);
                mma16816(acc[mf][2 * g + 1], afr[mf], bfr[g][2], bfr[g][3]);
            }
        }
    }

#pragma unroll
    for (int mf = 0; mf < 4; ++mf) {
#pragma unroll
        for (int nf = 0; nf < 4; ++nf) {
            int i = i0 + wm * 64 + mf * 16 + (lane >> 2);
            int j = j0 + wn * 32 + nf * 8 + (lane & 3) * 2;
            size_t o = ((size_t)b * HWSZ + i) * HWSZ + j;
            *(float2*)(g_S + o) = make_float2(acc[mf][nf][0], acc[mf][nf][1]);
            *(float2*)(g_S + o + (size_t)8 * HWSZ) = make_float2(acc[mf][nf][2], acc[mf][nf][3]);
        }
    }
}

// ---------------------------------------------------------------------------
// Kernel 4: softmax rows of g_S -> g_P (fp16)
// ---------------------------------------------------------------------------
__global__ void __launch_bounds__(256) softmax_kernel() {
    __shared__ float red[8];
    int t = threadIdx.x;
    int b = blockIdx.y;
    int i = blockIdx.x;
    const float* row = g_S + ((size_t)b * HWSZ + i) * HWSZ;
    float4 v[4];
#pragma unroll
    for (int r = 0; r < 4; ++r)
        v[r] = *(const float4*)(row + (t + r * 256) * 4);
    float m = -1e30f;
#pragma unroll
    for (int r = 0; r < 4; ++r)
        m = fmaxf(m, fmaxf(fmaxf(v[r].x, v[r].y), fmaxf(v[r].z, v[r].w)));
#pragma unroll
    for (int o = 16; o > 0; o >>= 1)
        m = fmaxf(m, __shfl_xor_sync(0xffffffffu, m, o));
    if ((t & 31) == 0) red[t >> 5] = m;
    __syncthreads();
    m = red[0];
#pragma unroll
    for (int w = 1; w < 8; ++w) m = fmaxf(m, red[w]);
    float s = 0.f;
#pragma unroll
    for (int r = 0; r < 4; ++r) {
        v[r].x = __expf(v[r].x - m);
        v[r].y = __expf(v[r].y - m);
        v[r].z = __expf(v[r].z - m);
        v[r].w = __expf(v[r].w - m);
        s += v[r].x + v[r].y + v[r].z + v[r].w;
    }
#pragma unroll
    for (int o = 16; o > 0; o >>= 1)
        s += __shfl_xor_sync(0xffffffffu, s, o);
    __syncthreads();
    if ((t & 31) == 0) red[t >> 5] = s;
    __syncthreads();
    s = 0.f;
#pragma unroll
    for (int w = 0; w < 8; ++w) s += red[w];
    float inv = 1.f / s;
    __half* prow = g_P + ((size_t)b * HWSZ + i) * HWSZ;
#pragma unroll
    for (int r = 0; r < 4; ++r) {
        int idx = (t + r * 256) * 4;
        u64 pk = 0ull;
        pk |= (u64)__half_as_ushort(__float2half(v[r].x * inv));
        pk |= (u64)__half_as_ushort(__float2half(v[r].y * inv)) << 16;
        pk |= (u64)__half_as_ushort(__float2half(v[r].z * inv)) << 32;
        pk |= (u64)__half_as_ushort(__float2half(v[r].w * inv)) << 48;
        *(u64*)(prow + idx) = pk;
    }
}

// ---------------------------------------------------------------------------
// Kernel 5: AV via mma.sync. A = Vhi+Vlo (both accumulated), B = P fp16.
// Tile M=128(c) x N=256(i), K-chunk 64, double-buffered cp.async.
// 8 warps as 2(M)x4(N), warp tile 64x64. Grid (2, 16, 4) = 128 blocks.
// ---------------------------------------------------------------------------
constexpr int AV_STAGE = 65536;          // Ahi 16KB | Alo 16KB | B 32KB
constexpr int AV_SMEM  = 2 * AV_STAGE;   // 128KB

__device__ __forceinline__ void av_load(u32 stbase, int t,
        const __half* Vh, const __half* Vl, const __half* Pp, int kc) {
    int arow = t & 127;
    int acb = (t >> 7) * 4;
    const __half* vh = Vh + (size_t)arow * HWSZ + kc * 64;
    const __half* vl = Vl + (size_t)arow * HWSZ + kc * 64;
    u32 Ah = stbase;
    u32 Al = stbase + 16384u;
    u32 Bs = stbase + 32768u;
    u32 ao = (u32)arow * 128u;
#pragma unroll
    for (int i = 0; i < 4; ++i) {
        int ch = acb + i;
        u32 sw = (u32)((ch ^ (arow & 7)) << 4);
        cpa16(Ah + ao + sw, vh + ch * 8);
        cpa16(Al + ao + sw, vl + ch * 8);
    }
    const __half* pr = Pp + (size_t)t * HWSZ + kc * 64;
    u32 bo = (u32)t * 128u;
#pragma unroll
    for (int ch = 0; ch < 8; ++ch) {
        u32 sw = (u32)((ch ^ (t & 7)) << 4);
        cpa16(Bs + bo + sw, pr + ch * 8);
    }
    cp_commit();
}

__global__ void __launch_bounds__(256, 1) av_mma_kernel(
        const float* __restrict__ inp,
        const float* __restrict__ gmm,
        float* __restrict__ outp) {
    extern __shared__ __align__(1024) char dynsm[];
    int t = threadIdx.x;
    int lane = t & 31;
    int wid = t >> 5;
    int mt = blockIdx.x;
    int nt = blockIdx.y;
    int b = blockIdx.z;
    int wm = wid & 1;
    int wn = wid >> 1;
    u32 base = smem_u32(dynsm);
    int c0 = mt * 128;
    int i0 = nt * 256;

    const __half* Vh = g_Vhi + ((size_t)b * CCH + c0) * HWSZ;
    const __half* Vl = g_Vlo + ((size_t)b * CCH + c0) * HWSZ;
    const __half* Pp = g_P + ((size_t)b * HWSZ + i0) * HWSZ;

    av_load(base, t, Vh, Vl, Pp, 0);
    av_load(base + AV_STAGE, t, Vh, Vl, Pp, 1);

    float acc[4][8][4];
#pragma unroll
    for (int a = 0; a < 4; ++a) {
#pragma unroll
        for (int n = 0; n < 8; ++n) {
#pragma unroll
            for (int e = 0; e < 4; ++e) acc[a][n][e] = 0.f;
        }
    }

    for (int kc = 0; kc < 64; ++kc) {
        if (kc < 63) {
            cp_wait1();
        } else {
            cp_wait0();
        }
        __syncthreads();
        u32 st = base + (u32)(kc & 1) * AV_STAGE;
        u32 Ah = st;
        u32 Al = st + 16384u;
        u32 Bs = st + 32768u;
#pragma unroll
        for (int s = 0; s < 4; ++s) {
            u32 ah[4][4];
            u32 al[4][4];
            u32 bfr[4][4];
#pragma unroll
            for (int mf = 0; mf < 4; ++mf) {
                int rowA = wm * 64 + mf * 16 + (lane & 15);
                int ch = 2 * s + (lane >> 4);
                u32 off = (u32)rowA * 128u + (u32)((ch ^ (rowA & 7)) << 4);
                ldm_x4(ah[mf], Ah + off);
                ldm_x4(al[mf], Al + off);
            }
#pragma unroll
            for (int g = 0; g < 4; ++g) {
                int rowB = wn * 64 + g * 16 + (lane & 7) + ((lane >> 4) << 3);
                int ch = 2 * s + ((lane >> 3) & 1);
                u32 off = (u32)rowB * 128u + (u32)((ch ^ (rowB & 7)) << 4);
                ldm_x4(bfr[g], Bs + off);
            }
#pragma unroll
            for (int mf = 0; mf < 4; ++mf) {
#pragma unroll
                for (int g = 0; g < 4; ++g) {
                    mma16816(acc[mf][2 * g],     ah[mf], bfr[g][0], bfr[g][1]);
                    mma16816(acc[mf][2 * g + 1], ah[mf], bfr[g][2], bfr[g][3]);
                    mma16816(acc[mf][2 * g],     al[mf], bfr[g][0], bfr[g][1]);
                    mma16816(acc[mf][2 * g + 1], al[mf], bfr[g][2], bfr[g][3]);
                }
            }
        }
        __syncthreads();
        if (kc + 2 < 64) {
            av_load(base + (u32)(kc & 1) * AV_STAGE, t, Vh, Vl, Pp, kc + 2);
        }
    }

    float g = gmm[0];
#pragma unroll
    for (int mf = 0; mf < 4; ++mf) {
#pragma unroll
        for (int nf = 0; nf < 8; ++nf) {
            int c = c0 + wm * 64 + mf * 16 + (lane >> 2);
            int i = i0 + wn * 64 + nf * 8 + (lane & 3) * 2;
            size_t o1 = ((size_t)b * CCH + c) * HWSZ + i;
            float2 iv = *(const float2*)(inp + o1);
            float2 ov;
            ov.x = fmaf(g, acc[mf][nf][0], iv.x);
            ov.y = fmaf(g, acc[mf][nf][1], iv.y);
            *(float2*)(outp + o1) = ov;
            size_t o2 = o1 + (size_t)8 * HWSZ;
            iv = *(const float2*)(inp + o2);
            ov.x = fmaf(g, acc[mf][nf][2], iv.x);
            ov.y = fmaf(g, acc[mf][nf][3], iv.y);
            *(float2*)(outp + o2) = ov;
        }
    }
}

// ---------------------------------------------------------------------------
extern "C" void kernel_launch(void* const* d_in, const int* in_sizes, int n_in,
                              void* d_out, int out_size) {
    const float* inp   = (const float*)d_in[0];
    const float* orig  = (const float*)d_in[1];
    const float* wq    = (const float*)d_in[2];
    const float* bq    = (const float*)d_in[3];
    const float* wk    = (const float*)d_in[4];
    const float* bk    = (const float*)d_in[5];
    const float* wv    = (const float*)d_in[6];
    const float* bv    = (const float*)d_in[7];
    const float* gamma = (const float*)d_in[8];
    float* outp = (float*)d_out;

    cudaFuncSetAttribute(av_mma_kernel,
                         cudaFuncAttributeMaxDynamicSharedMemorySize, AV_SMEM);

    proj_qk_kernel<<<dim3(HWSZ / 64, BATCH), 256>>>(inp, wq, bq, wk, bk);
    proj_v_kernel<<<dim3(HWSZ / 128, CCH / 64, BATCH), 256>>>(orig, wv, bv);
    qk_mma_kernel<<<dim3(32, 32, BATCH), 256>>>();
    softmax_kernel<<<dim3(HWSZ, BATCH), 256>>>();
    av_mma_kernel<<<dim3(2, 16, BATCH), 256, AV_SMEM>>>(inp, gamma, outp);
}